// round 16
// baseline (speedup 1.0000x reference)
#include <cuda_runtime.h>

#define DIM      64
#define KC       512
#define ROWS     128          // z rows per tile
#define KCHUNK   128          // codebook codes per smem chunk
#define NCHUNK   (KC / KCHUNK)
#define NTHREADS 128
#define ZS_LD    132          // 132*4B: 16B-aligned rows, conflict-free
#define ES_LD    132
#define SMEM_FLOATS (DIM*ZS_LD + DIM*ES_LD + KC + ROWS)
#define SMEM_BYTES  (SMEM_FLOATS * 4)

// ---- packed f32x2 helpers (ptxas never emits FFMA2 on its own) ----
#define FMA2(acc, a, b) asm("fma.rn.f32x2 %0, %1, %2, %0;" : "+l"(acc) : "l"(a), "l"(b))
#define DUP2(dst, x)    asm("mov.b64 %0, {%1, %1};" : "=l"(dst) : "r"(x))
#define UNPK(lo, hi, v) asm("mov.b64 {%0, %1}, %2;" : "=r"(lo), "=r"(hi) : "l"(v))

__device__ unsigned int g_tile_ctr;

__global__ void vq_reset() { g_tile_ctr = 0; }

__global__ void __launch_bounds__(NTHREADS, 3)
vq_kernel(const float* __restrict__ z, const float* __restrict__ cb,
          float* __restrict__ out, int n_rows) {
    extern __shared__ __align__(16) float sm[];
    float* ZS = sm;                   // [DIM][ZS_LD]  z tile transposed
    float* ES = ZS + DIM * ZS_LD;     // [DIM][ES_LD]  cb chunk transposed
    float* CN = ES + DIM * ES_LD;     // [KC]          ||e_k||^2
    float* ZN = CN + KC;              // [ROWS]        ||z_r||^2
    __shared__ int s_tile;

    const int tid = threadIdx.x;
    const int cx  = tid & 15;         // code group: 8 codes as 2 float4 spans
    const int ry  = tid >> 4;         // row group: 16 rows (8 packed pairs)

    // Codebook norms, reference rounding order (rounded mul, rounded add, d ascending).
    for (int k = tid; k < KC; k += NTHREADS) {
        const float* row = cb + k * DIM;
        float acc = 0.f;
        #pragma unroll 1
        for (int d = 0; d < DIM; d++) {
            float e = row[d];
            acc = __fadd_rn(acc, __fmul_rn(e, e));
        }
        CN[k] = acc;
    }

    const int ntiles = n_rows / ROWS;
    for (;;) {
        __syncthreads();   // prior tile's readers done; CN visible on first pass
        if (tid == 0) s_tile = (int)atomicAdd(&g_tile_ctr, 1u);
        __syncthreads();
        const int tile = s_tile;
        if (tile >= ntiles) break;

        const float4* zt4 = reinterpret_cast<const float4*>(z + (size_t)tile * (ROWS * DIM));
        // Z tile transposed; r-major item map -> conflict-free STS.
        for (int i = tid; i < ROWS * DIM / 4; i += NTHREADS) {
            int r  = i & (ROWS - 1);
            int c4 = i >> 7;
            float4 v = zt4[r * (DIM / 4) + c4];
            int d0 = c4 * 4;
            ZS[(d0 + 0) * ZS_LD + r] = v.x;
            ZS[(d0 + 1) * ZS_LD + r] = v.y;
            ZS[(d0 + 2) * ZS_LD + r] = v.z;
            ZS[(d0 + 3) * ZS_LD + r] = v.w;
        }
        __syncthreads();
        // Row norms: same sequential rounding chain as reference's sum(z*z).
        {
            float acc = 0.f;
            #pragma unroll 1
            for (int d = 0; d < DIM; d++) {
                float a = ZS[d * ZS_LD + tid];
                acc = __fadd_rn(acc, __fmul_rn(a, a));
            }
            ZN[tid] = acc;
        }
        // (ZN published by the sync at the top of the chunk loop)

        float minv[16]; int mini[16];
        #pragma unroll
        for (int i = 0; i < 16; i++) { minv[i] = __int_as_float(0x7f800000); mini[i] = 0; }

        #pragma unroll 1
        for (int kc = 0; kc < NCHUNK; kc++) {
            __syncthreads();   // prev chunk's ES readers done (also publishes ZN on kc=0)
            const float4* cbc4 =
                reinterpret_cast<const float4*>(cb + (size_t)(kc * KCHUNK) * DIM);
            for (int i = tid; i < KCHUNK * DIM / 4; i += NTHREADS) {
                int kl = i & (KCHUNK - 1);
                int c4 = i >> 7;
                float4 v = cbc4[kl * (DIM / 4) + c4];
                int d0 = c4 * 4;
                ES[(d0 + 0) * ES_LD + kl] = v.x;
                ES[(d0 + 1) * ES_LD + kl] = v.y;
                ES[(d0 + 2) * ES_LD + kl] = v.z;
                ES[(d0 + 3) * ES_LD + kl] = v.w;
            }
            __syncthreads();

            // 16x8 microtile, row-pair packed: acc2[rp][c] = rows (2rp,2rp+1), code c.
            // A row-pairs come pre-packed from contiguous ZS rows (no DUP needed);
            // only the 8 B values are duplicated. No explicit prefetch: with 12
            // warps/SM (occ 3), inter-warp parallelism covers the LDS latency.
            unsigned long long acc2[8][8];
            #pragma unroll
            for (int i = 0; i < 8; i++)
                #pragma unroll
                for (int j = 0; j < 8; j++) acc2[i][j] = 0ull;

            const float* zp = ZS + ry * 16;
            const float* ep = ES + cx * 4;

            #pragma unroll 4
            for (int d = 0; d < DIM; d++) {
                ulonglong2 A0 = *reinterpret_cast<const ulonglong2*>(zp + d * ZS_LD);
                ulonglong2 A1 = *reinterpret_cast<const ulonglong2*>(zp + d * ZS_LD + 4);
                ulonglong2 A2 = *reinterpret_cast<const ulonglong2*>(zp + d * ZS_LD + 8);
                ulonglong2 A3 = *reinterpret_cast<const ulonglong2*>(zp + d * ZS_LD + 12);
                float4     B0 = *reinterpret_cast<const float4*>(ep + d * ES_LD);
                float4     B1 = *reinterpret_cast<const float4*>(ep + d * ES_LD + 64);

                unsigned long long ap[8] = {A0.x, A0.y, A1.x, A1.y, A2.x, A2.y, A3.x, A3.y};
                float bv[8] = {B0.x, B0.y, B0.z, B0.w, B1.x, B1.y, B1.z, B1.w};
                unsigned long long bd[8];
                #pragma unroll
                for (int c = 0; c < 8; c++) DUP2(bd[c], __float_as_uint(bv[c]));
                #pragma unroll
                for (int rp = 0; rp < 8; rp++)
                    #pragma unroll
                    for (int c = 0; c < 8; c++) FMA2(acc2[rp][c], ap[rp], bd[c]);
            }

            // Epilogue: s = fl(fl(zn - 2*dot) + cn); FFMA(-2,dot,zn) bit-identical since
            // 2*dot is exact. Thread scan ascending k (c ascending), strict <.
            const int kb = kc * KCHUNK + cx * 4;
            float4 c0 = *reinterpret_cast<const float4*>(CN + kb);
            float4 c1 = *reinterpret_cast<const float4*>(CN + kb + 64);
            float cn[8] = {c0.x, c0.y, c0.z, c0.w, c1.x, c1.y, c1.z, c1.w};
            #pragma unroll
            for (int rp = 0; rp < 8; rp++) {
                float zn0 = ZN[ry * 16 + 2 * rp];
                float zn1 = ZN[ry * 16 + 2 * rp + 1];
                #pragma unroll
                for (int c = 0; c < 8; c++) {
                    unsigned int lo, hi;
                    UNPK(lo, hi, acc2[rp][c]);
                    float s0 = __fadd_rn(__fmaf_rn(-2.0f, __uint_as_float(lo), zn0), cn[c]);
                    float s1 = __fadd_rn(__fmaf_rn(-2.0f, __uint_as_float(hi), zn1), cn[c]);
                    int k = kb + (c >> 2) * 64 + (c & 3);
                    if (s0 < minv[2 * rp])     { minv[2 * rp]     = s0; mini[2 * rp]     = k; }
                    if (s1 < minv[2 * rp + 1]) { minv[2 * rp + 1] = s1; mini[2 * rp + 1] = k; }
                }
            }
        }

        // Reduce across the 16 cx lanes per row (lower index wins ties).
        #pragma unroll
        for (int i = 0; i < 16; i++) {
            float v  = minv[i];
            int  idx = mini[i];
            #pragma unroll
            for (int off = 8; off > 0; off >>= 1) {
                float vo = __shfl_xor_sync(0xffffffffu, v, off);
                int   io = __shfl_xor_sync(0xffffffffu, idx, off);
                if (vo < v || (vo == v && io < idx)) { v = vo; idx = io; }
            }
            // Output buffer is float32 — exact for idx <= 511.
            if (cx == 0) out[tile * ROWS + ry * 16 + i] = (float)idx;
        }
    }
}

extern "C" void kernel_launch(void* const* d_in, const int* in_sizes, int n_in,
                              void* d_out, int out_size) {
    int cb_idx = (n_in > 1 && in_sizes[1] == KC * DIM) ? 1 : 0;
    int z_idx  = 1 - cb_idx;
    const float* z  = (const float*)d_in[z_idx];    // z_e_x  [32,4096,64] f32
    const float* cb = (const float*)d_in[cb_idx];   // codebook [512,64]  f32
    int n_rows = in_sizes[z_idx] / DIM;             // 131072

    cudaFuncSetAttribute(vq_kernel, cudaFuncAttributeMaxDynamicSharedMemorySize, SMEM_BYTES);
    vq_reset<<<1, 1>>>();
    vq_kernel<<<444, NTHREADS, SMEM_BYTES>>>(z, cb, (float*)d_out, n_rows);
}